// round 1
// baseline (speedup 1.0000x reference)
#include <cuda_runtime.h>
#include <math.h>

#define N0 2048
#define D0 3
#define N1 1024
#define D1 5
#define TILE 16

// Scratch (device globals: allocation-free per harness rules)
__device__ float g_kn0[N0 * D0 * D0];
__device__ float g_inv0[N0 * D0 * D0];
__device__ float g_kn1[N1 * D1 * D1];
__device__ float g_inv1[N1 * D1 * D1];
__device__ double g_sum0;
__device__ double g_sum1;

__global__ void zero_sums_kernel() {
    g_sum0 = 0.0;
    g_sum1 = 0.0;
}

// ---------------- Layer 0 prep: normalize + 3x3 adjugate inverse ----------------
__global__ void prep0_kernel(const float* __restrict__ k0) {
    int i = blockIdx.x * blockDim.x + threadIdx.x;
    if (i >= N0) return;
    float a[9];
    float ss = 0.f;
#pragma unroll
    for (int t = 0; t < 9; t++) {
        a[t] = k0[i * 9 + t];
        ss += a[t] * a[t];
    }
    float rn = 1.f / (sqrtf(ss) + 1e-8f);
#pragma unroll
    for (int t = 0; t < 9; t++) {
        a[t] *= rn;
        g_kn0[i * 9 + t] = a[t];
    }
    // adjugate inverse
    float c00 = a[4] * a[8] - a[5] * a[7];
    float c10 = a[5] * a[6] - a[3] * a[8];
    float c20 = a[3] * a[7] - a[4] * a[6];
    float det = a[0] * c00 + a[1] * c10 + a[2] * c20;
    float id = 1.f / det;
    g_inv0[i * 9 + 0] = c00 * id;
    g_inv0[i * 9 + 1] = (a[2] * a[7] - a[1] * a[8]) * id;
    g_inv0[i * 9 + 2] = (a[1] * a[5] - a[2] * a[4]) * id;
    g_inv0[i * 9 + 3] = c10 * id;
    g_inv0[i * 9 + 4] = (a[0] * a[8] - a[2] * a[6]) * id;
    g_inv0[i * 9 + 5] = (a[2] * a[3] - a[0] * a[5]) * id;
    g_inv0[i * 9 + 6] = c20 * id;
    g_inv0[i * 9 + 7] = (a[1] * a[6] - a[0] * a[7]) * id;
    g_inv0[i * 9 + 8] = (a[0] * a[4] - a[1] * a[3]) * id;
}

// ---------------- Layer 1 prep: normalize + 5x5 Gauss-Jordan with pivoting ----------------
__global__ void prep1_kernel(const float* __restrict__ k1) {
    int i = blockIdx.x * blockDim.x + threadIdx.x;
    if (i >= N1) return;
    float a[5][5], b[5][5];
    float ss = 0.f;
#pragma unroll
    for (int r = 0; r < 5; r++)
#pragma unroll
        for (int c = 0; c < 5; c++) {
            float v = k1[i * 25 + r * 5 + c];
            a[r][c] = v;
            ss += v * v;
        }
    float rn = 1.f / (sqrtf(ss) + 1e-8f);
#pragma unroll
    for (int r = 0; r < 5; r++)
#pragma unroll
        for (int c = 0; c < 5; c++) {
            a[r][c] *= rn;
            g_kn1[i * 25 + r * 5 + c] = a[r][c];
            b[r][c] = (r == c) ? 1.f : 0.f;
        }
    for (int col = 0; col < 5; col++) {
        // partial pivot
        int p = col;
        float mx = fabsf(a[col][col]);
        for (int r = col + 1; r < 5; r++) {
            float v = fabsf(a[r][col]);
            if (v > mx) { mx = v; p = r; }
        }
        if (p != col) {
            for (int c = 0; c < 5; c++) {
                float t = a[col][c]; a[col][c] = a[p][c]; a[p][c] = t;
                t = b[col][c]; b[col][c] = b[p][c]; b[p][c] = t;
            }
        }
        float piv = 1.f / a[col][col];
        for (int c = 0; c < 5; c++) { a[col][c] *= piv; b[col][c] *= piv; }
        for (int r = 0; r < 5; r++) {
            if (r == col) continue;
            float f = a[r][col];
            for (int c = 0; c < 5; c++) {
                a[r][c] -= f * a[col][c];
                b[r][c] -= f * b[col][c];
            }
        }
    }
#pragma unroll
    for (int r = 0; r < 5; r++)
#pragma unroll
        for (int c = 0; c < 5; c++)
            g_inv1[i * 25 + r * 5 + c] = b[r][c];
}

// ---------------- Pairwise loss: sum_{i>j} relu(1 - ||I - inv[i] kn[j]||_F) ----------------
template <int LAYER>
__global__ void pair_kernel() {
    constexpr int N = (LAYER == 0) ? N0 : N1;
    constexpr int D = (LAYER == 0) ? D0 : D1;
    constexpr int DD = D * D;

    const int ti = blockIdx.y;
    const int tj = blockIdx.x;
    if (tj > ti) return;  // strictly lower-triangular tiles (incl. diagonal tiles)

    const float* invg = (LAYER == 0) ? g_inv0 : g_inv1;
    const float* kng  = (LAYER == 0) ? g_kn0  : g_kn1;
    double* sumg      = (LAYER == 0) ? &g_sum0 : &g_sum1;

    __shared__ float sInv[TILE * DD];
    __shared__ float sKn[TILE * DD];

    const int tx = threadIdx.x;  // j within tile
    const int ty = threadIdx.y;  // i within tile
    const int t = ty * TILE + tx;

    for (int idx = t; idx < TILE * DD; idx += TILE * TILE) {
        sInv[idx] = invg[ti * TILE * DD + idx];
        sKn[idx]  = kng[tj * TILE * DD + idx];
    }
    __syncthreads();

    const int i = ti * TILE + ty;
    const int j = tj * TILE + tx;

    float val = 0.f;
    if (i > j) {
        const float* A = &sInv[ty * DD];  // inv[i], D x D row-major
        const float* B = &sKn[tx * DD];   // kn[j]
        float s = 0.f;
#pragma unroll
        for (int r = 0; r < D; r++) {
#pragma unroll
            for (int c = 0; c < D; c++) {
                float acc = 0.f;
#pragma unroll
                for (int b = 0; b < D; b++)
                    acc = fmaf(A[r * D + b], B[b * D + c], acc);
                float dlt = ((r == c) ? 1.f : 0.f) - acc;
                s = fmaf(dlt, dlt, s);
            }
        }
        if (s < 1.f) val = 1.f - sqrtf(s);
    }

    // block reduction: warp shuffle, then shared, then one double atomic
    unsigned m = 0xFFFFFFFFu;
#pragma unroll
    for (int off = 16; off > 0; off >>= 1)
        val += __shfl_down_sync(m, val, off);

    __shared__ float warp_sums[TILE * TILE / 32];
    const int warp = t / 32;
    const int lane = t % 32;
    if (lane == 0) warp_sums[warp] = val;
    __syncthreads();
    if (t == 0) {
        float bs = 0.f;
#pragma unroll
        for (int w = 0; w < TILE * TILE / 32; w++) bs += warp_sums[w];
        atomicAdd(sumg, (double)bs);
    }
}

__global__ void finalize_kernel(float* out) {
    double l0 = 2.0 * g_sum0 / ((double)N0 * (double)(N0 - 1));
    double l1 = 2.0 * g_sum1 / ((double)N1 * (double)(N1 - 1));
    out[0] = (float)(0.5 * (l0 + l1));
}

extern "C" void kernel_launch(void* const* d_in, const int* in_sizes, int n_in,
                              void* d_out, int out_size) {
    const float* k0 = (const float*)d_in[0];
    const float* k1 = (const float*)d_in[1];
    float* out = (float*)d_out;

    zero_sums_kernel<<<1, 1>>>();
    prep0_kernel<<<(N0 + 127) / 128, 128>>>(k0);
    prep1_kernel<<<(N1 + 127) / 128, 128>>>(k1);

    dim3 blk(TILE, TILE);
    dim3 g0(N0 / TILE, N0 / TILE);
    dim3 g1(N1 / TILE, N1 / TILE);
    pair_kernel<0><<<g0, blk>>>();
    pair_kernel<1><<<g1, blk>>>();

    finalize_kernel<<<1, 1>>>(out);
}

// round 2
// speedup vs baseline: 1.5339x; 1.5339x over previous
#include <cuda_runtime.h>
#include <math.h>

#define N0 2048
#define D0 3
#define N1 1024
#define D1 5

#define TS 32                       // pair-tile side (i and j)
#define T0 (N0 / TS)                // 64 tiles per dim, layer0
#define T1 (N1 / TS)                // 32 tiles per dim, layer1
#define NBLK0 (T0 * (T0 + 1) / 2)   // 2080
#define NBLK1 (T1 * (T1 + 1) / 2)   // 528
#define NTHREADS 256

// Scratch (device globals: allocation-free per harness rules)
__device__ float g_kn0[N0 * D0 * D0];
__device__ float g_inv0[N0 * D0 * D0];
__device__ float g_kn1[N1 * D1 * D1];
__device__ float g_inv1[N1 * D1 * D1];
__device__ double g_sum0;
__device__ double g_sum1;

// ---------------- Fused prep: normalize + invert both layers, zero accumulators ----------------
// Grid: blocks [0,16) -> layer0 (128 matrices each), [16,24) -> layer1.
__global__ void prep_kernel(const float* __restrict__ k0, const float* __restrict__ k1) {
    if (blockIdx.x == 0 && threadIdx.x == 0) {
        g_sum0 = 0.0;
        g_sum1 = 0.0;
    }
    int gid = blockIdx.x * blockDim.x + threadIdx.x;
    if (blockIdx.x < 16) {
        int i = gid;
        if (i >= N0) return;
        float a[9];
        float ss = 0.f;
#pragma unroll
        for (int t = 0; t < 9; t++) {
            a[t] = k0[i * 9 + t];
            ss = fmaf(a[t], a[t], ss);
        }
        float rn = 1.f / (sqrtf(ss) + 1e-8f);
#pragma unroll
        for (int t = 0; t < 9; t++) {
            a[t] *= rn;
            g_kn0[i * 9 + t] = a[t];
        }
        float c00 = a[4] * a[8] - a[5] * a[7];
        float c10 = a[5] * a[6] - a[3] * a[8];
        float c20 = a[3] * a[7] - a[4] * a[6];
        float det = a[0] * c00 + a[1] * c10 + a[2] * c20;
        float id = 1.f / det;
        g_inv0[i * 9 + 0] = c00 * id;
        g_inv0[i * 9 + 1] = (a[2] * a[7] - a[1] * a[8]) * id;
        g_inv0[i * 9 + 2] = (a[1] * a[5] - a[2] * a[4]) * id;
        g_inv0[i * 9 + 3] = c10 * id;
        g_inv0[i * 9 + 4] = (a[0] * a[8] - a[2] * a[6]) * id;
        g_inv0[i * 9 + 5] = (a[2] * a[3] - a[0] * a[5]) * id;
        g_inv0[i * 9 + 6] = c20 * id;
        g_inv0[i * 9 + 7] = (a[1] * a[6] - a[0] * a[7]) * id;
        g_inv0[i * 9 + 8] = (a[0] * a[4] - a[1] * a[3]) * id;
    } else {
        int i = gid - 16 * 128;
        if (i >= N1) return;
        float a[5][5], b[5][5];
        float ss = 0.f;
#pragma unroll
        for (int r = 0; r < 5; r++)
#pragma unroll
            for (int c = 0; c < 5; c++) {
                float v = k1[i * 25 + r * 5 + c];
                a[r][c] = v;
                ss = fmaf(v, v, ss);
            }
        float rn = 1.f / (sqrtf(ss) + 1e-8f);
#pragma unroll
        for (int r = 0; r < 5; r++)
#pragma unroll
            for (int c = 0; c < 5; c++) {
                a[r][c] *= rn;
                g_kn1[i * 25 + r * 5 + c] = a[r][c];
                b[r][c] = (r == c) ? 1.f : 0.f;
            }
        for (int col = 0; col < 5; col++) {
            int p = col;
            float mx = fabsf(a[col][col]);
            for (int r = col + 1; r < 5; r++) {
                float v = fabsf(a[r][col]);
                if (v > mx) { mx = v; p = r; }
            }
            if (p != col) {
                for (int c = 0; c < 5; c++) {
                    float t = a[col][c]; a[col][c] = a[p][c]; a[p][c] = t;
                    t = b[col][c]; b[col][c] = b[p][c]; b[p][c] = t;
                }
            }
            float piv = 1.f / a[col][col];
            for (int c = 0; c < 5; c++) { a[col][c] *= piv; b[col][c] *= piv; }
            for (int r = 0; r < 5; r++) {
                if (r == col) continue;
                float f = a[r][col];
                for (int c = 0; c < 5; c++) {
                    a[r][c] = fmaf(-f, a[col][c], a[r][c]);
                    b[r][c] = fmaf(-f, b[col][c], b[r][c]);
                }
            }
        }
#pragma unroll
        for (int r = 0; r < 5; r++)
#pragma unroll
            for (int c = 0; c < 5; c++)
                g_inv1[i * 25 + r * 5 + c] = b[r][c];
    }
}

// ---------------- Pairwise loss body ----------------
// sum_{i>j} relu(1 - ||I - inv[i] kn[j]||_F), triangular tile decode,
// B=kn[j] register-resident per thread, A=inv[i] warp-broadcast from shared.
template <int D>
__device__ __forceinline__ void pair_body(int b, const float* __restrict__ invg,
                                          const float* __restrict__ kng, double* sumg) {
    constexpr int DD = D * D;

    // triangular decode: b = ti*(ti+1)/2 + tj, tj <= ti
    int ti = (int)((sqrtf(8.f * (float)b + 1.f) - 1.f) * 0.5f);
    while ((ti + 1) * (ti + 2) / 2 <= b) ti++;
    while (ti * (ti + 1) / 2 > b) ti--;
    int tj = b - ti * (ti + 1) / 2;

    __shared__ float sA[TS * DD];
    __shared__ float sB[TS * DD];
    __shared__ float warp_sums[NTHREADS / 32];

    const int t = threadIdx.x;
    for (int idx = t; idx < TS * DD; idx += NTHREADS) {
        sA[idx] = invg[ti * TS * DD + idx];
        sB[idx] = kng[tj * TS * DD + idx];
    }
    __syncthreads();

    const int w = t >> 5;       // warp 0..7, owns 4 consecutive i's
    const int l = t & 31;       // lane = j within tile
    const int j = tj * TS + l;
    const bool diag = (ti == tj);

    // B = kn[j] in registers
    float B[DD];
#pragma unroll
    for (int q = 0; q < DD; q++) B[q] = sB[l * DD + q];

    float val = 0.f;
#pragma unroll
    for (int ii = 0; ii < 4; ii++) {
        const int il = w * 4 + ii;
        const int i = ti * TS + il;
        if (diag && i <= j) continue;
        const float* A = &sA[il * DD];  // warp-uniform -> broadcast
        float s = 0.f;
#pragma unroll
        for (int r = 0; r < D; r++) {
#pragma unroll
            for (int c = 0; c < D; c++) {
                float acc = 0.f;
#pragma unroll
                for (int k = 0; k < D; k++)
                    acc = fmaf(A[r * D + k], B[k * D + c], acc);
                float dlt = ((r == c) ? 1.f : 0.f) - acc;
                s = fmaf(dlt, dlt, s);
            }
        }
        if (s < 1.f) val += 1.f - sqrtf(s);
    }

    // reduce
#pragma unroll
    for (int off = 16; off > 0; off >>= 1)
        val += __shfl_down_sync(0xFFFFFFFFu, val, off);
    if (l == 0) warp_sums[w] = val;
    __syncthreads();
    if (t == 0) {
        float bs = 0.f;
#pragma unroll
        for (int ww = 0; ww < NTHREADS / 32; ww++) bs += warp_sums[ww];
        atomicAdd(sumg, (double)bs);
    }
}

__global__ void __launch_bounds__(NTHREADS) pair_all_kernel() {
    int b = blockIdx.x;
    if (b < NBLK0)
        pair_body<D0>(b, g_inv0, g_kn0, &g_sum0);
    else
        pair_body<D1>(b - NBLK0, g_inv1, g_kn1, &g_sum1);
}

__global__ void finalize_kernel(float* out) {
    double l0 = 2.0 * g_sum0 / ((double)N0 * (double)(N0 - 1));
    double l1 = 2.0 * g_sum1 / ((double)N1 * (double)(N1 - 1));
    out[0] = (float)(0.5 * (l0 + l1));
}

extern "C" void kernel_launch(void* const* d_in, const int* in_sizes, int n_in,
                              void* d_out, int out_size) {
    const float* k0 = (const float*)d_in[0];
    const float* k1 = (const float*)d_in[1];
    float* out = (float*)d_out;

    prep_kernel<<<24, 128>>>(k0, k1);
    pair_all_kernel<<<NBLK0 + NBLK1, NTHREADS>>>();
    finalize_kernel<<<1, 1>>>(out);
}

// round 3
// speedup vs baseline: 1.8261x; 1.1905x over previous
#include <cuda_runtime.h>
#include <math.h>

#define N0 2048
#define D0 3
#define N1 1024
#define D1 5

#define TS 32                       // pair-tile side (i and j)
#define T0 (N0 / TS)                // 64 tiles per dim, layer0
#define T1 (N1 / TS)                // 32 tiles per dim, layer1
#define NBLK0 (T0 * (T0 + 1) / 2)   // 2080
#define NBLK1 (T1 * (T1 + 1) / 2)   // 528
#define NBLK  (NBLK0 + NBLK1)       // 2608
#define NTHREADS 256

// Scratch (device globals: allocation-free per harness rules)
__device__ float g_kn0[N0 * D0 * D0];
__device__ float g_inv0[N0 * D0 * D0];
__device__ float g_kn1[N1 * D1 * D1];
__device__ float g_inv1[N1 * D1 * D1];
__device__ double g_sum0;
__device__ double g_sum1;
__device__ unsigned int g_done = 0;

// ---------------- Fused prep: normalize + invert both layers, zero accumulators ----------------
// 32-thread blocks: blocks [0,64) -> layer0, [64,96) -> layer1. All indices static
// so both matrices live entirely in registers (no local-memory spills).
__global__ void __launch_bounds__(32) prep_kernel(const float* __restrict__ k0,
                                                  const float* __restrict__ k1) {
    if (blockIdx.x == 0 && threadIdx.x == 0) {
        g_sum0 = 0.0;
        g_sum1 = 0.0;
    }
    int gid = blockIdx.x * 32 + threadIdx.x;
    if (blockIdx.x < 64) {
        int i = gid;
        float a[9];
        float ss = 0.f;
#pragma unroll
        for (int t = 0; t < 9; t++) {
            a[t] = k0[i * 9 + t];
            ss = fmaf(a[t], a[t], ss);
        }
        float rn = 1.f / (sqrtf(ss) + 1e-8f);
#pragma unroll
        for (int t = 0; t < 9; t++) {
            a[t] *= rn;
            g_kn0[i * 9 + t] = a[t];
        }
        float c00 = a[4] * a[8] - a[5] * a[7];
        float c10 = a[5] * a[6] - a[3] * a[8];
        float c20 = a[3] * a[7] - a[4] * a[6];
        float det = a[0] * c00 + a[1] * c10 + a[2] * c20;
        float id = 1.f / det;
        g_inv0[i * 9 + 0] = c00 * id;
        g_inv0[i * 9 + 1] = (a[2] * a[7] - a[1] * a[8]) * id;
        g_inv0[i * 9 + 2] = (a[1] * a[5] - a[2] * a[4]) * id;
        g_inv0[i * 9 + 3] = c10 * id;
        g_inv0[i * 9 + 4] = (a[0] * a[8] - a[2] * a[6]) * id;
        g_inv0[i * 9 + 5] = (a[2] * a[3] - a[0] * a[5]) * id;
        g_inv0[i * 9 + 6] = c20 * id;
        g_inv0[i * 9 + 7] = (a[1] * a[6] - a[0] * a[7]) * id;
        g_inv0[i * 9 + 8] = (a[0] * a[4] - a[1] * a[3]) * id;
    } else {
        int i = gid - 64 * 32;
        float a[5][5], b[5][5];
        float ss = 0.f;
#pragma unroll
        for (int r = 0; r < 5; r++)
#pragma unroll
            for (int c = 0; c < 5; c++) {
                float v = k1[i * 25 + r * 5 + c];
                a[r][c] = v;
                ss = fmaf(v, v, ss);
            }
        float rn = 1.f / (sqrtf(ss) + 1e-8f);
#pragma unroll
        for (int r = 0; r < 5; r++)
#pragma unroll
            for (int c = 0; c < 5; c++) {
                a[r][c] *= rn;
                g_kn1[i * 25 + r * 5 + c] = a[r][c];
                b[r][c] = (r == c) ? 1.f : 0.f;
            }
        // Gauss-Jordan, fully static indices. Pivoting via predicated
        // compare-swaps: after the inner chain, row `col` holds the column max.
#pragma unroll
        for (int col = 0; col < 5; col++) {
#pragma unroll
            for (int r = col + 1; r < 5; r++) {
                bool sw = fabsf(a[r][col]) > fabsf(a[col][col]);
#pragma unroll
                for (int c = 0; c < 5; c++) {
                    float t0 = a[col][c], t1 = a[r][c];
                    a[col][c] = sw ? t1 : t0;
                    a[r][c]   = sw ? t0 : t1;
                    float u0 = b[col][c], u1 = b[r][c];
                    b[col][c] = sw ? u1 : u0;
                    b[r][c]   = sw ? u0 : u1;
                }
            }
            float piv = 1.f / a[col][col];
#pragma unroll
            for (int c = 0; c < 5; c++) {
                a[col][c] *= piv;
                b[col][c] *= piv;
            }
#pragma unroll
            for (int r = 0; r < 5; r++) {
                if (r == col) continue;
                float f = a[r][col];
#pragma unroll
                for (int c = 0; c < 5; c++) {
                    a[r][c] = fmaf(-f, a[col][c], a[r][c]);
                    b[r][c] = fmaf(-f, b[col][c], b[r][c]);
                }
            }
        }
#pragma unroll
        for (int r = 0; r < 5; r++)
#pragma unroll
            for (int c = 0; c < 5; c++)
                g_inv1[i * 25 + r * 5 + c] = b[r][c];
    }
}

// ---------------- Pairwise loss body ----------------
template <int D>
__device__ __forceinline__ float pair_body(int b, const float* __restrict__ invg,
                                           const float* __restrict__ kng) {
    constexpr int DD = D * D;

    // triangular decode: b = ti*(ti+1)/2 + tj, tj <= ti
    int ti = (int)((sqrtf(8.f * (float)b + 1.f) - 1.f) * 0.5f);
    while ((ti + 1) * (ti + 2) / 2 <= b) ti++;
    while (ti * (ti + 1) / 2 > b) ti--;
    int tj = b - ti * (ti + 1) / 2;

    __shared__ float sA[TS * DD];
    __shared__ float sB[TS * DD];

    const int t = threadIdx.x;
    for (int idx = t; idx < TS * DD; idx += NTHREADS) {
        sA[idx] = invg[ti * TS * DD + idx];
        sB[idx] = kng[tj * TS * DD + idx];
    }
    __syncthreads();

    const int w = t >> 5;       // warp 0..7, owns 4 consecutive i's
    const int l = t & 31;       // lane = j within tile
    const int j = tj * TS + l;
    const bool diag = (ti == tj);

    float B[DD];
#pragma unroll
    for (int q = 0; q < DD; q++) B[q] = sB[l * DD + q];

    float val = 0.f;
#pragma unroll
    for (int ii = 0; ii < 4; ii++) {
        const int il = w * 4 + ii;
        const int i = ti * TS + il;
        if (diag && i <= j) continue;
        const float* A = &sA[il * DD];  // warp-uniform -> broadcast
        float s = 0.f;
#pragma unroll
        for (int r = 0; r < D; r++) {
#pragma unroll
            for (int c = 0; c < D; c++) {
                float acc = 0.f;
#pragma unroll
                for (int k = 0; k < D; k++)
                    acc = fmaf(A[r * D + k], B[k * D + c], acc);
                float dlt = ((r == c) ? 1.f : 0.f) - acc;
                s = fmaf(dlt, dlt, s);
            }
        }
        if (s < 1.f) val += 1.f - sqrtf(s);
    }
    return val;
}

__global__ void __launch_bounds__(NTHREADS) pair_all_kernel(float* __restrict__ out) {
    int b = blockIdx.x;
    float val;
    double* sumg;
    if (b < NBLK0) {
        val = pair_body<D0>(b, g_inv0, g_kn0);
        sumg = &g_sum0;
    } else {
        val = pair_body<D1>(b - NBLK0, g_inv1, g_kn1);
        sumg = &g_sum1;
    }

    // block reduction
#pragma unroll
    for (int off = 16; off > 0; off >>= 1)
        val += __shfl_down_sync(0xFFFFFFFFu, val, off);

    __shared__ float warp_sums[NTHREADS / 32];
    const int t = threadIdx.x;
    if ((t & 31) == 0) warp_sums[t >> 5] = val;
    __syncthreads();

    if (t == 0) {
        float bs = 0.f;
#pragma unroll
        for (int ww = 0; ww < NTHREADS / 32; ww++) bs += warp_sums[ww];
        atomicAdd(sumg, (double)bs);
        __threadfence();
        unsigned int done = atomicAdd(&g_done, 1u);
        if (done == NBLK - 1) {
            // last block: all partial sums globally visible
            __threadfence();
            double s0 = *(volatile double*)&g_sum0;
            double s1 = *(volatile double*)&g_sum1;
            double l0 = 2.0 * s0 / ((double)N0 * (double)(N0 - 1));
            double l1 = 2.0 * s1 / ((double)N1 * (double)(N1 - 1));
            out[0] = (float)(0.5 * (l0 + l1));
            g_done = 0;  // reset for next graph replay
        }
    }
}

extern "C" void kernel_launch(void* const* d_in, const int* in_sizes, int n_in,
                              void* d_out, int out_size) {
    const float* k0 = (const float*)d_in[0];
    const float* k1 = (const float*)d_in[1];
    float* out = (float*)d_out;

    prep_kernel<<<96, 32>>>(k0, k1);
    pair_all_kernel<<<NBLK, NTHREADS>>>(out);
}

// round 4
// speedup vs baseline: 1.9280x; 1.0558x over previous
#include <cuda_runtime.h>
#include <math.h>

#define N0 2048
#define D0 3
#define N1 1024
#define D1 5

#define TS 32
#define T0 (N0 / TS)                // 64
#define T1 (N1 / TS)                // 32
#define NBLK0 (T0 * (T0 + 1) / 2)   // 2080
#define NBLK1 (T1 * (T1 + 1) / 2)   // 528
#define NBLK  (NBLK0 + NBLK1)       // 2608
#define PAIR_THREADS 128
#define GRID_PAIR 888               // 148 SMs * 6

typedef unsigned long long ull;

// Scratch (device globals: allocation-free per harness rules)
__device__ float g_kn0[N0 * D0 * D0];
__device__ float g_inv0[N0 * D0 * D0];
__device__ float g_kn1[N1 * D1 * D1];
__device__ float g_inv1[N1 * D1 * D1];
__device__ double g_sum0;
__device__ double g_sum1;
__device__ unsigned int g_done = 0;

// ---------------- packed f32x2 helpers (FFMA2: PTX-only) ----------------
__device__ __forceinline__ ull f2pack(float lo, float hi) {
    ull r;
    asm("mov.b64 %0, {%1, %2};" : "=l"(r) : "f"(lo), "f"(hi));
    return r;
}
__device__ __forceinline__ void f2unpack(ull v, float& lo, float& hi) {
    asm("mov.b64 {%0, %1}, %2;" : "=f"(lo), "=f"(hi) : "l"(v));
}
__device__ __forceinline__ ull fma2(ull a, ull b, ull c) {
    ull d;
    asm("fma.rn.f32x2 %0, %1, %2, %3;" : "=l"(d) : "l"(a), "l"(b), "l"(c));
    return d;
}
__device__ __forceinline__ ull add2(ull a, ull b) {
    ull d;
    asm("add.rn.f32x2 %0, %1, %2;" : "=l"(d) : "l"(a), "l"(b));
    return d;
}

// ---------------- Fused prep (unchanged from R3: register-resident, static indices) ----------------
__global__ void __launch_bounds__(32) prep_kernel(const float* __restrict__ k0,
                                                  const float* __restrict__ k1) {
    if (blockIdx.x == 0 && threadIdx.x == 0) {
        g_sum0 = 0.0;
        g_sum1 = 0.0;
    }
    int gid = blockIdx.x * 32 + threadIdx.x;
    if (blockIdx.x < 64) {
        int i = gid;
        float a[9];
        float ss = 0.f;
#pragma unroll
        for (int t = 0; t < 9; t++) {
            a[t] = k0[i * 9 + t];
            ss = fmaf(a[t], a[t], ss);
        }
        float rn = 1.f / (sqrtf(ss) + 1e-8f);
#pragma unroll
        for (int t = 0; t < 9; t++) {
            a[t] *= rn;
            g_kn0[i * 9 + t] = a[t];
        }
        float c00 = a[4] * a[8] - a[5] * a[7];
        float c10 = a[5] * a[6] - a[3] * a[8];
        float c20 = a[3] * a[7] - a[4] * a[6];
        float det = a[0] * c00 + a[1] * c10 + a[2] * c20;
        float id = 1.f / det;
        g_inv0[i * 9 + 0] = c00 * id;
        g_inv0[i * 9 + 1] = (a[2] * a[7] - a[1] * a[8]) * id;
        g_inv0[i * 9 + 2] = (a[1] * a[5] - a[2] * a[4]) * id;
        g_inv0[i * 9 + 3] = c10 * id;
        g_inv0[i * 9 + 4] = (a[0] * a[8] - a[2] * a[6]) * id;
        g_inv0[i * 9 + 5] = (a[2] * a[3] - a[0] * a[5]) * id;
        g_inv0[i * 9 + 6] = c20 * id;
        g_inv0[i * 9 + 7] = (a[1] * a[6] - a[0] * a[7]) * id;
        g_inv0[i * 9 + 8] = (a[0] * a[4] - a[1] * a[3]) * id;
    } else {
        int i = gid - 64 * 32;
        float a[5][5], b[5][5];
        float ss = 0.f;
#pragma unroll
        for (int r = 0; r < 5; r++)
#pragma unroll
            for (int c = 0; c < 5; c++) {
                float v = k1[i * 25 + r * 5 + c];
                a[r][c] = v;
                ss = fmaf(v, v, ss);
            }
        float rn = 1.f / (sqrtf(ss) + 1e-8f);
#pragma unroll
        for (int r = 0; r < 5; r++)
#pragma unroll
            for (int c = 0; c < 5; c++) {
                a[r][c] *= rn;
                g_kn1[i * 25 + r * 5 + c] = a[r][c];
                b[r][c] = (r == c) ? 1.f : 0.f;
            }
#pragma unroll
        for (int col = 0; col < 5; col++) {
#pragma unroll
            for (int r = col + 1; r < 5; r++) {
                bool sw = fabsf(a[r][col]) > fabsf(a[col][col]);
#pragma unroll
                for (int c = 0; c < 5; c++) {
                    float t0 = a[col][c], t1 = a[r][c];
                    a[col][c] = sw ? t1 : t0;
                    a[r][c]   = sw ? t0 : t1;
                    float u0 = b[col][c], u1 = b[r][c];
                    b[col][c] = sw ? u1 : u0;
                    b[r][c]   = sw ? u0 : u1;
                }
            }
            float piv = 1.f / a[col][col];
#pragma unroll
            for (int c = 0; c < 5; c++) {
                a[col][c] *= piv;
                b[col][c] *= piv;
            }
#pragma unroll
            for (int r = 0; r < 5; r++) {
                if (r == col) continue;
                float f = a[r][col];
#pragma unroll
                for (int c = 0; c < 5; c++) {
                    a[r][c] = fmaf(-f, a[col][c], a[r][c]);
                    b[r][c] = fmaf(-f, b[col][c], b[r][c]);
                }
            }
        }
#pragma unroll
        for (int r = 0; r < 5; r++)
#pragma unroll
            for (int c = 0; c < 5; c++)
                g_inv1[i * 25 + r * 5 + c] = b[r][c];
    }
}

// ---------------- One 32x32 pair tile, packed over i-pairs ----------------
// sAT holds NEGATED inv, transposed: sAT[q*TS + i].  sB row-major: sB[j*DD + q].
template <int D>
__device__ __forceinline__ void pair_tile(int b, const float* __restrict__ invg,
                                          const float* __restrict__ kng,
                                          float* sAT, float* sB, float& val) {
    constexpr int DD = D * D;

    // triangular decode: b = ti*(ti+1)/2 + tj, tj <= ti
    int ti = (int)((sqrtf(8.f * (float)b + 1.f) - 1.f) * 0.5f);
    while ((ti + 1) * (ti + 2) / 2 <= b) ti++;
    while (ti * (ti + 1) / 2 > b) ti--;
    int tj = b - ti * (ti + 1) / 2;

    const int t = threadIdx.x;
    __syncthreads();  // previous tile's shared reads complete
    for (int idx = t; idx < TS * DD; idx += PAIR_THREADS) {
        int i = idx / DD;
        int q = idx - i * DD;
        sAT[q * TS + i] = -invg[ti * TS * DD + idx];  // negate A at staging
        sB[idx] = kng[tj * TS * DD + idx];
    }
    __syncthreads();

    const int w = t >> 5;   // warp 0..3 -> i range [w*8, w*8+8)
    const int l = t & 31;   // lane -> j
    const int j = tj * TS + l;
    const bool diag = (ti == tj);

    // B duplicated into both packed halves
    ull B2[DD];
#pragma unroll
    for (int q = 0; q < DD; q++) {
        float bq = sB[l * DD + q];
        B2[q] = f2pack(bq, bq);
    }
    const ull eye2 = f2pack(1.f, 1.f);

#pragma unroll
    for (int p = 0; p < 4; p++) {
        const int il = w * 8 + 2 * p;  // even -> 8B-aligned LDS.64
        ull s2 = 0;                    // packed (0.f, 0.f)
#pragma unroll
        for (int r = 0; r < D; r++) {
            ull A2[D];
#pragma unroll
            for (int k = 0; k < D; k++)
                A2[k] = *reinterpret_cast<const ull*>(&sAT[(r * D + k) * TS + il]);
#pragma unroll
            for (int c = 0; c < D; c++) {
                ull acc = 0;  // accumulates -C[r][c] (A pre-negated)
#pragma unroll
                for (int k = 0; k < D; k++)
                    acc = fma2(A2[k], B2[k * D + c], acc);
                if (r == c) acc = add2(acc, eye2);  // delta = I - C
                s2 = fma2(acc, acc, s2);
            }
        }
        float s_lo, s_hi;
        f2unpack(s2, s_lo, s_hi);
        const int i0 = ti * TS + il;
        if ((!diag || i0 > j) && s_lo < 1.f) val += 1.f - sqrtf(s_lo);
        if ((!diag || i0 + 1 > j) && s_hi < 1.f) val += 1.f - sqrtf(s_hi);
    }
}

// ---------------- Persistent pair kernel ----------------
__global__ void __launch_bounds__(PAIR_THREADS) pair_all_kernel(float* __restrict__ out) {
    __shared__ __align__(16) float sAT[TS * D1 * D1];  // sized for D=5
    __shared__ __align__(16) float sB[TS * D1 * D1];
    __shared__ float warp_sums[2][PAIR_THREADS / 32];

    float val0 = 0.f, val1 = 0.f;

    for (int job = blockIdx.x; job < NBLK; job += GRID_PAIR) {
        if (job < NBLK0)
            pair_tile<D0>(job, g_inv0, g_kn0, sAT, sB, val0);
        else
            pair_tile<D1>(job - NBLK0, g_inv1, g_kn1, sAT, sB, val1);
    }

    // block reduction of both accumulators
#pragma unroll
    for (int off = 16; off > 0; off >>= 1) {
        val0 += __shfl_down_sync(0xFFFFFFFFu, val0, off);
        val1 += __shfl_down_sync(0xFFFFFFFFu, val1, off);
    }
    const int t = threadIdx.x;
    __syncthreads();  // shared arrays done being used as tiles
    if ((t & 31) == 0) {
        warp_sums[0][t >> 5] = val0;
        warp_sums[1][t >> 5] = val1;
    }
    __syncthreads();
    if (t == 0) {
        float b0 = 0.f, b1 = 0.f;
#pragma unroll
        for (int ww = 0; ww < PAIR_THREADS / 32; ww++) {
            b0 += warp_sums[0][ww];
            b1 += warp_sums[1][ww];
        }
        if (b0 != 0.f) atomicAdd(&g_sum0, (double)b0);
        if (b1 != 0.f) atomicAdd(&g_sum1, (double)b1);
        __threadfence();
        unsigned int done = atomicAdd(&g_done, 1u);
        if (done == GRID_PAIR - 1) {
            __threadfence();
            double s0 = *(volatile double*)&g_sum0;
            double s1 = *(volatile double*)&g_sum1;
            double l0 = 2.0 * s0 / ((double)N0 * (double)(N0 - 1));
            double l1 = 2.0 * s1 / ((double)N1 * (double)(N1 - 1));
            out[0] = (float)(0.5 * (l0 + l1));
            g_done = 0;  // reset for next graph replay
        }
    }
}

extern "C" void kernel_launch(void* const* d_in, const int* in_sizes, int n_in,
                              void* d_out, int out_size) {
    const float* k0 = (const float*)d_in[0];
    const float* k1 = (const float*)d_in[1];
    float* out = (float*)d_out;

    prep_kernel<<<96, 32>>>(k0, k1);
    pair_all_kernel<<<GRID_PAIR, PAIR_THREADS>>>(out);
}